// round 15
// baseline (speedup 1.0000x reference)
#include <cuda_runtime.h>

typedef unsigned int u32;
typedef unsigned long long u64;

namespace {
constexpr int B_     = 2;
constexpr int N_     = 8192;
constexpr int KNN    = 10;
constexpr int KP1    = 11;
constexpr int KS     = 12;                    // sample-chain depth
constexpr int SPLIT  = 4;
constexpr int QPB    = 128;
constexpr int THREADS = QPB * SPLIT;          // 512
constexpr int SUBLEN  = N_ / SPLIT;           // 2048 (1024 pairs/thread)
constexpr int GROUP   = 16;                   // candidates per group (8 pairs)
constexpr int NGROUPS = SUBLEN / GROUP;       // 128
constexpr int WARM    = 6;                    // per-pair-exact warm-up groups
constexpr int SAMPLE  = 24;                   // groups in sample phase (384 cands)
constexpr int BPB     = N_ / QPB;             // 64
constexpr int NBLOCKS = B_ * BPB;             // 128 -> 1 block/SM
constexpr int GTOT    = NBLOCKS * THREADS;    // 65536
constexpr int LOGCAP  = 256;
constexpr u64 STRIDEB = (u64)GTOT * 16ull;    // 1MB = 2^20 (16B pair entries)
constexpr int SMEM_BYTES = N_ * 16;           // 128KB point staging
}

__device__ float g_partials[NBLOCKS];
__device__ uint4 g_log[(size_t)LOGCAP * GTOT];   // 268MB static scratch (legal)

__device__ __forceinline__ u64 pk2(float a, float b) {
    u64 r; asm("mov.b64 %0, {%1, %2};" : "=l"(r) : "f"(a), "f"(b)); return r;
}
__device__ __forceinline__ u64 fma2(u64 a, u64 b, u64 c) {
    u64 d; asm("fma.rn.f32x2 %0, %1, %2, %3;" : "=l"(d) : "l"(a), "l"(b), "l"(c)); return d;
}
__device__ __forceinline__ u64 add2(u64 a, u64 b) {
    u64 d; asm("add.rn.f32x2 %0, %1, %2;" : "=l"(d) : "l"(a), "l"(b)); return d;
}
__device__ __forceinline__ void unpk(u64 v, u32& lo, u32& hi) {
    asm("mov.b64 {%0, %1}, %2;" : "=r"(lo), "=r"(hi) : "l"(v));
}
__device__ __forceinline__ u32 umn(u32 a, u32 b) { return a < b ? a : b; }
__device__ __forceinline__ float uasf(u32 x) { return __uint_as_float(x); }

// Branchless 12-deep float sorted-insert (keys strictly positive).
__device__ __forceinline__ void ins12f(float c, float (&kd)[KS]) {
#pragma unroll
    for (int t = 0; t < KS; ++t) {
        const float lo = fminf(c, kd[t]);
        const float hi = fmaxf(c, kd[t]);
        kd[t] = lo; c = hi;
    }
}
// u32 11-deep variant for recovery/merge (positive-float bits + tags).
__device__ __forceinline__ void ins11u(u32 c, u32 (&kd)[KP1]) {
#pragma unroll
    for (int t = 0; t < KP1; ++t) {
        const u32 lo = umn(c, kd[t]);
        const u32 hi = (c > kd[t]) ? c : kd[t];
        kd[t] = lo; c = hi;
    }
}

// Predicated PAIR log: if pm < thr, store {klo, khi, jabs, jabs}, bump addr.
__device__ __forceinline__ void logpair(u64& addr, float pm, float thr,
                                        u32 klo, u32 khi, u32 jabs) {
    asm volatile(
        "{\n\t.reg .pred p;\n\t"
        "setp.lt.f32 p, %1, %2;\n\t"
        "@p st.global.v4.b32 [%0], {%3, %4, %5, %5};\n\t"
        "@p add.u64 %0, %0, %6;\n\t}"
        : "+l"(addr)
        : "f"(pm), "f"(thr), "r"(klo), "r"(khi), "r"(jabs), "l"(STRIDEB)
        : "memory");
}

__global__ __launch_bounds__(THREADS, 1)
void knn_lap_loss_kernel(const float* __restrict__ p1, const float* __restrict__ p2) {
    extern __shared__ unsigned char smem_raw[];
    float4* buf = reinterpret_cast<float4*>(smem_raw);

    const int tid   = threadIdx.x;
    const int gtid  = blockIdx.x * THREADS + tid;
    const int b     = blockIdx.x / BPB;
    const int qbase = (blockIdx.x % BPB) * QPB;
    const float* __restrict__ p1b = p1 + (size_t)b * N_ * 3;
    const float* __restrict__ p2b = p2 + (size_t)b * N_ * 3;

    // ---- Phase 1: stage pairs: buf[2p]={x0,x1,y0,y1}, buf[2p+1]={z0,z1,w0,w1} ----
    for (int p = tid; p < N_ / 2; p += THREADS) {
        const int a = 2 * p, c = 2 * p + 1;
        float xa = p1b[a*3+0], ya = p1b[a*3+1], za = p1b[a*3+2];
        float xb = p1b[c*3+0], yb = p1b[c*3+1], zb = p1b[c*3+2];
        float wa = fmaf(xa, xa, fmaf(ya, ya, za * za));
        float wb = fmaf(xb, xb, fmaf(yb, yb, zb * zb));
        buf[2*p]   = make_float4(xa, xb, ya, yb);
        buf[2*p+1] = make_float4(za, zb, wa, wb);
    }
    __syncthreads();

    // ---- Query constants. key = dist^2 + 1 > 0 strictly. ----
    const int q   = tid & (QPB - 1);    // consecutive within warp -> LDS broadcast
    const int sub = tid >> 7;           // 0..3 (constant within warp)
    const int qi  = qbase + q;
    float qx, qy, qz, qw;
    {
        const int p = qi >> 1, h = qi & 1;
        const float4 A = buf[2*p], C = buf[2*p+1];
        qx = h ? A.y : A.x;  qy = h ? A.w : A.z;
        qz = h ? C.y : C.x;  qw = h ? C.w : C.z;
    }
    const u64 m2x2 = pk2(-2.0f*qx, -2.0f*qx);
    const u64 m2y2 = pk2(-2.0f*qy, -2.0f*qy);
    const u64 m2z2 = pk2(-2.0f*qz, -2.0f*qz);
    const float qb = qw + 1.0f;
    const u64 qb2  = pk2(qb, qb);

    // 12-deep sample chain of pair-mins from DISTINCT pairs. After the sample
    // phase, thr = kd[11] satisfies: >=12 distinct pairs have pm <= thr =>
    // >=12 keys <= thr in sample => full-range 11th key <= thr. Frozen-thr
    // logging (pm < thr logs BOTH keys) then has full recall.
    float kd[KS];
#pragma unroll
    for (int t = 0; t < KS; ++t) kd[t] = 3.0e38f;

    u64 addr        = (u64)(g_log + gtid);
    const u64 base  = addr;
    const u64 limit = base + (u64)(LOGCAP - 8) * STRIDEB;

    const int jbeg = sub * SUBLEN;

    // ---- Phase 2a: warm-up (per-pair fresh thr + chain). First 12 pairs always
    // log => recovery has >= 24 keys. ----
    for (int g = 0; g < WARM; ++g) {
        const int jg = jbeg + g * GROUP;
        const int pb = jg >> 1;
#pragma unroll
        for (int pp = 0; pp < GROUP / 2; ++pp) {
            const float4 A = buf[2*(pb+pp)], C = buf[2*(pb+pp)+1];
            u64 acc = add2(pk2(C.z, C.w), qb2);
            acc = fma2(pk2(A.x, A.y), m2x2, acc);
            acc = fma2(pk2(A.z, A.w), m2y2, acc);
            acc = fma2(pk2(C.x, C.y), m2z2, acc);
            u32 klo, khi; unpk(acc, klo, khi);
            const float pm = fminf(uasf(klo), uasf(khi));
            logpair(addr, pm, kd[KS-1], klo, khi, (u32)(jg + 2*pp));
            ins12f(pm, kd);
        }
    }

    // ---- Phase 2b: rest of sample phase (per-group thr + min-tree + chain) ----
    for (int g = WARM; g < SAMPLE; ++g) {
        const int jg = jbeg + g * GROUP;
        const int pb = jg >> 1;
        const float thr = kd[KS-1];
        float pm[GROUP / 2];
#pragma unroll
        for (int pp = 0; pp < GROUP / 2; ++pp) {
            const float4 A = buf[2*(pb+pp)], C = buf[2*(pb+pp)+1];
            u64 acc = add2(pk2(C.z, C.w), qb2);
            acc = fma2(pk2(A.x, A.y), m2x2, acc);
            acc = fma2(pk2(A.z, A.w), m2y2, acc);
            acc = fma2(pk2(C.x, C.y), m2z2, acc);
            u32 klo, khi; unpk(acc, klo, khi);
            pm[pp] = fminf(uasf(klo), uasf(khi));
            logpair(addr, pm[pp], thr, klo, khi, (u32)(jg + 2*pp));
        }
        const float m0 = fminf(fminf(pm[0], pm[1]), fminf(pm[2], pm[3]));
        const float m1 = fminf(fminf(pm[4], pm[5]), fminf(pm[6], pm[7]));
        ins12f(fminf(m0, m1), kd);   // group-min = pm of a distinct pair
    }

    // ---- Phase 2c: FROZEN-threshold main scan — no chain, no min-tree.
    // Per pair: 2 LDS + 4 FFMA2 + 1 FMNMX + predicated {SETP, STG.128, add}. ----
    const float thrF = kd[KS-1];
    for (int g = SAMPLE; g < NGROUPS; ++g) {
        const int jg = jbeg + g * GROUP;
        const int pb = jg >> 1;
        const float thr = (addr <= limit) ? thrF : 0.0f;
#pragma unroll
        for (int pp = 0; pp < GROUP / 2; ++pp) {
            const float4 A = buf[2*(pb+pp)], C = buf[2*(pb+pp)+1];
            u64 acc = add2(pk2(C.z, C.w), qb2);
            acc = fma2(pk2(A.x, A.y), m2x2, acc);
            acc = fma2(pk2(A.z, A.w), m2y2, acc);
            acc = fma2(pk2(C.x, C.y), m2z2, acc);
            u32 klo, khi; unpk(acc, klo, khi);
            const float pm = fminf(uasf(klo), uasf(khi));
            logpair(addr, pm, thr, klo, khi, (u32)(jg + 2*pp));
        }
    }

    // ---- Phase 3: exact recovery. Tag = (slot<<1)|half in 9 masked key bits. ----
    const u32 cnt = (u32)((addr - base) >> 20);   // STRIDEB = 2^20
    u32 rc[KP1];
#pragma unroll
    for (int t = 0; t < KP1; ++t) rc[t] = 0xFFFFFFFFu;
    for (u32 i = 0; i < cnt; ++i) {
        const uint4 e = *reinterpret_cast<const uint4*>(base + (u64)i * STRIDEB);
        ins11u((e.x & 0xFFFFFE00u) | (i << 1) | 0u, rc);
        ins11u((e.y & 0xFFFFFE00u) | (i << 1) | 1u, rc);
    }

    __syncthreads();   // done reading staged points; smem reused below

    // ---- Phase 4: decode indices, dump sorted lists to smem ----
    u32* sval = reinterpret_cast<u32*>(smem_raw);
    u32* sidx = sval + THREADS * KP1;
    {
        const int dbase = (q * SPLIT + sub) * KP1;
#pragma unroll
        for (int r = 0; r < KP1; ++r) {
            const u32 slot = (rc[r] >> 1) & 0xFFu;
            const u32 h    = rc[r] & 1u;
            const uint4 e  = *reinterpret_cast<const uint4*>(base + (u64)slot * STRIDEB);
            sval[dbase + r] = rc[r];
            sidx[dbase + r] = e.z + h;
        }
    }
    __syncthreads();

    // ---- Phase 5: sub==0 threads 4-way merge + gather + per-query L1 ----
    float acc = 0.0f;
    if (sub == 0) {
        const u32* v0 = sval + (q * SPLIT + 0) * KP1;
        const u32* v1 = sval + (q * SPLIT + 1) * KP1;
        const u32* v2 = sval + (q * SPLIT + 2) * KP1;
        const u32* v3 = sval + (q * SPLIT + 3) * KP1;
        const u32* i0 = sidx + (q * SPLIT + 0) * KP1;
        const u32* i1 = sidx + (q * SPLIT + 1) * KP1;
        const u32* i2 = sidx + (q * SPLIT + 2) * KP1;
        const u32* i3 = sidx + (q * SPLIT + 3) * KP1;

        int c0 = 0, c1 = 0, c2 = 0, c3 = 0;
        u32 nidx[KP1];
#pragma unroll
        for (int r = 0; r < KP1; ++r) {
            const u32 h0 = v0[c0], h1 = v1[c1], h2 = v2[c2], h3 = v3[c3];
            const u32 m = umn(umn(h0, h1), umn(h2, h3));
            u32 bi;
            if (m == h0)      { bi = i0[c0]; ++c0; }
            else if (m == h1) { bi = i1[c1]; ++c1; }
            else if (m == h2) { bi = i2[c2]; ++c2; }
            else              { bi = i3[c3]; ++c3; }
            nidx[r] = bi;
        }

        // nidx[0] is self (key = 1.0, global min) -> neighbors are nidx[1..10]
        float sx = 0.0f, sy = 0.0f, sz = 0.0f;
#pragma unroll
        for (int r = 1; r < KP1; ++r) {
            const int bi = (int)nidx[r];
            sx += p1b[bi*3+0] - p2b[bi*3+0];
            sy += p1b[bi*3+1] - p2b[bi*3+1];
            sz += p1b[bi*3+2] - p2b[bi*3+2];
        }
        const float dqx = p1b[qi*3+0] - p2b[qi*3+0];
        const float dqy = p1b[qi*3+1] - p2b[qi*3+1];
        const float dqz = p1b[qi*3+2] - p2b[qi*3+2];
        const float inv_k = 1.0f / (float)KNN;
        acc = fabsf(fmaf(sx, inv_k, -dqx))
            + fabsf(fmaf(sy, inv_k, -dqy))
            + fabsf(fmaf(sz, inv_k, -dqz));
    }

    // ---- Phase 6: deterministic block reduction ----
    float* red = reinterpret_cast<float*>(sval + 2 * THREADS * KP1);
    red[tid] = acc;
    __syncthreads();
#pragma unroll
    for (int s = THREADS / 2; s > 0; s >>= 1) {
        if (tid < s) red[tid] += red[tid + s];
        __syncthreads();
    }
    if (tid == 0) g_partials[blockIdx.x] = red[0];
}

__global__ void final_reduce_kernel(float* __restrict__ out) {
    __shared__ float s[NBLOCKS];
    const int t = threadIdx.x;
    s[t] = g_partials[t];
    __syncthreads();
#pragma unroll
    for (int st = NBLOCKS / 2; st > 0; st >>= 1) {
        if (t < st) s[t] += s[t + st];
        __syncthreads();
    }
    if (t == 0) out[0] = s[0] * (1.0f / (float)(B_ * N_ * 3));
}

extern "C" void kernel_launch(void* const* d_in, const int* in_sizes, int n_in,
                              void* d_out, int out_size) {
    const float* p1 = (const float*)d_in[0];
    const float* p2 = (const float*)d_in[1];
    (void)in_sizes; (void)n_in; (void)out_size;

    cudaFuncSetAttribute(knn_lap_loss_kernel,
                         cudaFuncAttributeMaxDynamicSharedMemorySize, SMEM_BYTES);
    knn_lap_loss_kernel<<<NBLOCKS, THREADS, SMEM_BYTES>>>(p1, p2);
    final_reduce_kernel<<<1, NBLOCKS>>>((float*)d_out);
}

// round 16
// speedup vs baseline: 1.6574x; 1.6574x over previous
#include <cuda_runtime.h>

typedef unsigned int u32;
typedef unsigned long long u64;

namespace {
constexpr int B_     = 2;
constexpr int N_     = 8192;
constexpr int KNN    = 10;
constexpr int KP1    = 11;
constexpr int SPLIT  = 4;
constexpr int QPB    = 128;
constexpr int THREADS = QPB * SPLIT;          // 512
constexpr int SUBLEN  = N_ / SPLIT;           // 2048 (1024 pairs/thread)
constexpr int GROUP   = 16;                   // candidates per group (8 pairs)
constexpr int NGROUPS = SUBLEN / GROUP;       // 128
constexpr int WARM    = 6;                    // warm-up groups (96 candidates)
constexpr int BPB     = N_ / QPB;             // 64
constexpr int NBLOCKS = B_ * BPB;             // 128 -> 1 block/SM
constexpr int GTOT    = NBLOCKS * THREADS;    // 65536
constexpr int LOGCAP  = 160;
constexpr u64 STRIDEB = (u64)GTOT * 16ull;    // 1MB = 2^20 (16B pair entries)
constexpr int SMEM_BYTES = N_ * 16;           // 128KB point staging
}

__device__ float g_partials[NBLOCKS];
__device__ u32   g_arrive = 0;
__device__ uint4 g_log[(size_t)LOGCAP * GTOT];   // 160MB static scratch (legal)

__device__ __forceinline__ u64 pk2(float a, float b) {
    u64 r; asm("mov.b64 %0, {%1, %2};" : "=l"(r) : "f"(a), "f"(b)); return r;
}
__device__ __forceinline__ u64 fma2(u64 a, u64 b, u64 c) {
    u64 d; asm("fma.rn.f32x2 %0, %1, %2, %3;" : "=l"(d) : "l"(a), "l"(b), "l"(c)); return d;
}
__device__ __forceinline__ u64 add2(u64 a, u64 b) {
    u64 d; asm("add.rn.f32x2 %0, %1, %2;" : "=l"(d) : "l"(a), "l"(b)); return d;
}
__device__ __forceinline__ void unpk(u64 v, u32& lo, u32& hi) {
    asm("mov.b64 {%0, %1}, %2;" : "=r"(lo), "=r"(hi) : "l"(v));
}
__device__ __forceinline__ u32 umn(u32 a, u32 b) { return a < b ? a : b; }
__device__ __forceinline__ float uasf(u32 x) { return __uint_as_float(x); }

// Branchless float sorted-insert (keys strictly positive -> total order fine).
__device__ __forceinline__ void ins11f(float c, float (&kd)[KP1]) {
#pragma unroll
    for (int t = 0; t < KP1; ++t) {
        const float lo = fminf(c, kd[t]);
        const float hi = fmaxf(c, kd[t]);
        kd[t] = lo; c = hi;
    }
}
// u32 variant for recovery/merge (positive-float bit patterns + tags).
__device__ __forceinline__ void ins11u(u32 c, u32 (&kd)[KP1]) {
#pragma unroll
    for (int t = 0; t < KP1; ++t) {
        const u32 lo = umn(c, kd[t]);
        const u32 hi = (c > kd[t]) ? c : kd[t];
        kd[t] = lo; c = hi;
    }
}

// Predicated PAIR log: if pm < thr, store {klo, khi, jabs, jabs}, bump addr.
__device__ __forceinline__ void logpair(u64& addr, float pm, float thr,
                                        u32 klo, u32 khi, u32 jabs) {
    asm volatile(
        "{\n\t.reg .pred p;\n\t"
        "setp.lt.f32 p, %1, %2;\n\t"
        "@p st.global.v4.b32 [%0], {%3, %4, %5, %5};\n\t"
        "@p add.u64 %0, %0, %6;\n\t}"
        : "+l"(addr)
        : "f"(pm), "f"(thr), "r"(klo), "r"(khi), "r"(jabs), "l"(STRIDEB)
        : "memory");
}

__global__ __launch_bounds__(THREADS, 1)
void knn_lap_loss_kernel(const float* __restrict__ p1, const float* __restrict__ p2,
                         float* __restrict__ out) {
    extern __shared__ unsigned char smem_raw[];
    float4* buf = reinterpret_cast<float4*>(smem_raw);

    const int tid   = threadIdx.x;
    const int gtid  = blockIdx.x * THREADS + tid;
    const int b     = blockIdx.x / BPB;
    const int qbase = (blockIdx.x % BPB) * QPB;
    const float* __restrict__ p1b = p1 + (size_t)b * N_ * 3;
    const float* __restrict__ p2b = p2 + (size_t)b * N_ * 3;

    // ---- Phase 1: stage pairs: buf[2p]={x0,x1,y0,y1}, buf[2p+1]={z0,z1,w0,w1} ----
    for (int p = tid; p < N_ / 2; p += THREADS) {
        const int a = 2 * p, c = 2 * p + 1;
        float xa = p1b[a*3+0], ya = p1b[a*3+1], za = p1b[a*3+2];
        float xb = p1b[c*3+0], yb = p1b[c*3+1], zb = p1b[c*3+2];
        float wa = fmaf(xa, xa, fmaf(ya, ya, za * za));
        float wb = fmaf(xb, xb, fmaf(yb, yb, zb * zb));
        buf[2*p]   = make_float4(xa, xb, ya, yb);
        buf[2*p+1] = make_float4(za, zb, wa, wb);
    }
    __syncthreads();

    // ---- Query constants. key = dist^2 + 1 > 0 strictly. ----
    const int q   = tid & (QPB - 1);    // consecutive within warp -> LDS broadcast
    const int sub = tid >> 7;           // 0..3 (constant within warp)
    const int qi  = qbase + q;
    float qx, qy, qz, qw;
    {
        const int p = qi >> 1, h = qi & 1;
        const float4 A = buf[2*p], C = buf[2*p+1];
        qx = h ? A.y : A.x;  qy = h ? A.w : A.z;
        qz = h ? C.y : C.x;  qw = h ? C.w : C.z;
    }
    const u64 m2x2 = pk2(-2.0f*qx, -2.0f*qx);
    const u64 m2y2 = pk2(-2.0f*qy, -2.0f*qy);
    const u64 m2z2 = pk2(-2.0f*qz, -2.0f*qz);
    const float qb = qw + 1.0f;
    const u64 qb2  = pk2(qb, qb);

    float kd[KP1];
#pragma unroll
    for (int t = 0; t < KP1; ++t) kd[t] = 3.0e38f;

    u64 addr        = (u64)(g_log + gtid);
    const u64 base  = addr;
    const u64 limit = base + (u64)(LOGCAP - 16) * STRIDEB;

    const int jbeg = sub * SUBLEN;

    // ---- Phase 2a: exact warm-up (per-pair fresh thr; both keys into chain).
    // kd starts INF -> first pairs always log => recovery has >= 11 keys. ----
    for (int g = 0; g < WARM; ++g) {
        const int jg = jbeg + g * GROUP;
        const int pb = jg >> 1;
#pragma unroll
        for (int pp = 0; pp < GROUP / 2; ++pp) {
            const float4 A = buf[2*(pb+pp)], C = buf[2*(pb+pp)+1];
            u64 acc = add2(pk2(C.z, C.w), qb2);
            acc = fma2(pk2(A.x, A.y), m2x2, acc);
            acc = fma2(pk2(A.z, A.w), m2y2, acc);
            acc = fma2(pk2(C.x, C.y), m2z2, acc);
            u32 klo, khi; unpk(acc, klo, khi);
            const float pm = fminf(uasf(klo), uasf(khi));
            const float thr = (addr <= limit) ? kd[KP1-1] : 0.0f;
            logpair(addr, pm, thr, klo, khi, (u32)(jg + 2*pp));
            ins11f(uasf(klo), kd);
            ins11f(uasf(khi), kd);
        }
    }

    // ---- Phase 2b: main scan in SUPERBLOCKS of 32 candidates (16 pairs):
    // one thr refresh, one 15-op min-tree, one chain insert per superblock.
    // Superblock-min is a distinct key per superblock -> kd[10] still bounds
    // the true 11th key (11 distinct keys <= kd[10]). Recall-safe. ----
    for (int g = WARM; g < NGROUPS; g += 2) {
        const int jg = jbeg + g * GROUP;
        const int pb = jg >> 1;
        const float thr = (addr <= limit) ? kd[KP1-1] : 0.0f;
        float pm[16];
#pragma unroll
        for (int pp = 0; pp < 16; ++pp) {
            const float4 A = buf[2*(pb+pp)], C = buf[2*(pb+pp)+1];
            u64 acc = add2(pk2(C.z, C.w), qb2);
            acc = fma2(pk2(A.x, A.y), m2x2, acc);
            acc = fma2(pk2(A.z, A.w), m2y2, acc);
            acc = fma2(pk2(C.x, C.y), m2z2, acc);
            u32 klo, khi; unpk(acc, klo, khi);
            pm[pp] = fminf(uasf(klo), uasf(khi));
            logpair(addr, pm[pp], thr, klo, khi, (u32)(jg + 2*pp));
        }
        // 15-op min-tree over 16 pair-mins
        float m = fminf(pm[0], pm[1]);
        m = fminf(m, fminf(pm[2], pm[3]));
        float m2 = fminf(pm[4], pm[5]);
        m2 = fminf(m2, fminf(pm[6], pm[7]));
        float m3 = fminf(pm[8], pm[9]);
        m3 = fminf(m3, fminf(pm[10], pm[11]));
        float m4 = fminf(pm[12], pm[13]);
        m4 = fminf(m4, fminf(pm[14], pm[15]));
        ins11f(fminf(fminf(m, m2), fminf(m3, m4)), kd);
    }

    // ---- Phase 3: exact recovery. Tag = (slot<<1)|half in 9 masked key bits. ----
    const u32 cnt = (u32)((addr - base) >> 20);   // STRIDEB = 2^20
    u32 rc[KP1];
#pragma unroll
    for (int t = 0; t < KP1; ++t) rc[t] = 0xFFFFFFFFu;
    for (u32 i = 0; i < cnt; ++i) {
        const uint4 e = *reinterpret_cast<const uint4*>(base + (u64)i * STRIDEB);
        ins11u((e.x & 0xFFFFFE00u) | (i << 1) | 0u, rc);
        ins11u((e.y & 0xFFFFFE00u) | (i << 1) | 1u, rc);
    }

    __syncthreads();   // done reading staged points; smem reused below

    // ---- Phase 4: decode indices, dump sorted lists to smem ----
    u32* sval = reinterpret_cast<u32*>(smem_raw);
    u32* sidx = sval + THREADS * KP1;
    {
        const int dbase = (q * SPLIT + sub) * KP1;
#pragma unroll
        for (int r = 0; r < KP1; ++r) {
            const u32 slot = (rc[r] >> 1) & 0xFFu;
            const u32 h    = rc[r] & 1u;
            const uint4 e  = *reinterpret_cast<const uint4*>(base + (u64)slot * STRIDEB);
            sval[dbase + r] = rc[r];
            sidx[dbase + r] = e.z + h;
        }
    }
    __syncthreads();

    // ---- Phase 5: sub==0 threads 4-way merge + gather + per-query L1 ----
    float acc = 0.0f;
    if (sub == 0) {
        const u32* v0 = sval + (q * SPLIT + 0) * KP1;
        const u32* v1 = sval + (q * SPLIT + 1) * KP1;
        const u32* v2 = sval + (q * SPLIT + 2) * KP1;
        const u32* v3 = sval + (q * SPLIT + 3) * KP1;
        const u32* i0 = sidx + (q * SPLIT + 0) * KP1;
        const u32* i1 = sidx + (q * SPLIT + 1) * KP1;
        const u32* i2 = sidx + (q * SPLIT + 2) * KP1;
        const u32* i3 = sidx + (q * SPLIT + 3) * KP1;

        int c0 = 0, c1 = 0, c2 = 0, c3 = 0;
        u32 nidx[KP1];
#pragma unroll
        for (int r = 0; r < KP1; ++r) {
            const u32 h0 = v0[c0], h1 = v1[c1], h2 = v2[c2], h3 = v3[c3];
            const u32 m = umn(umn(h0, h1), umn(h2, h3));
            u32 bi;
            if (m == h0)      { bi = i0[c0]; ++c0; }
            else if (m == h1) { bi = i1[c1]; ++c1; }
            else if (m == h2) { bi = i2[c2]; ++c2; }
            else              { bi = i3[c3]; ++c3; }
            nidx[r] = bi;
        }

        // nidx[0] is self (key = 1.0, global min) -> neighbors are nidx[1..10]
        float sx = 0.0f, sy = 0.0f, sz = 0.0f;
#pragma unroll
        for (int r = 1; r < KP1; ++r) {
            const int bi = (int)nidx[r];
            sx += p1b[bi*3+0] - p2b[bi*3+0];
            sy += p1b[bi*3+1] - p2b[bi*3+1];
            sz += p1b[bi*3+2] - p2b[bi*3+2];
        }
        const float dqx = p1b[qi*3+0] - p2b[qi*3+0];
        const float dqy = p1b[qi*3+1] - p2b[qi*3+1];
        const float dqz = p1b[qi*3+2] - p2b[qi*3+2];
        const float inv_k = 1.0f / (float)KNN;
        acc = fabsf(fmaf(sx, inv_k, -dqx))
            + fabsf(fmaf(sy, inv_k, -dqy))
            + fabsf(fmaf(sz, inv_k, -dqz));
    }

    // ---- Phase 6: block reduction + fused deterministic final reduce ----
    float* red = reinterpret_cast<float*>(sval + 2 * THREADS * KP1);
    float* fin = red + THREADS;
    red[tid] = acc;
    __syncthreads();
#pragma unroll
    for (int s = THREADS / 2; s > 0; s >>= 1) {
        if (tid < s) red[tid] += red[tid + s];
        __syncthreads();
    }
    if (tid == 0) {
        __stcg(&g_partials[blockIdx.x], red[0]);
        __threadfence();
        const u32 prev = atomicAdd(&g_arrive, 1u);
        red[0] = (prev == (u32)(NBLOCKS - 1)) ? 1.0f : 0.0f;   // last-block flag
    }
    __syncthreads();
    if (red[0] != 0.0f) {
        // Last arriving block: all partials visible. Fixed-order tree -> deterministic.
        if (tid < NBLOCKS) fin[tid] = __ldcg(&g_partials[tid]);
        __syncthreads();
#pragma unroll
        for (int s = NBLOCKS / 2; s > 0; s >>= 1) {
            if (tid < s) fin[tid] += fin[tid + s];
            __syncthreads();
        }
        if (tid == 0) {
            out[0] = fin[0] * (1.0f / (float)(B_ * N_ * 3));
            g_arrive = 0;   // self-reset for next graph replay
        }
    }
}

extern "C" void kernel_launch(void* const* d_in, const int* in_sizes, int n_in,
                              void* d_out, int out_size) {
    const float* p1 = (const float*)d_in[0];
    const float* p2 = (const float*)d_in[1];
    (void)in_sizes; (void)n_in; (void)out_size;

    cudaFuncSetAttribute(knn_lap_loss_kernel,
                         cudaFuncAttributeMaxDynamicSharedMemorySize, SMEM_BYTES);
    knn_lap_loss_kernel<<<NBLOCKS, THREADS, SMEM_BYTES>>>(p1, p2, (float*)d_out);
}

// round 17
// speedup vs baseline: 1.8089x; 1.0914x over previous
#include <cuda_runtime.h>

typedef unsigned int u32;
typedef unsigned long long u64;

namespace {
constexpr int B_     = 2;
constexpr int N_     = 8192;
constexpr int KNN    = 10;
constexpr int KP1    = 11;
constexpr int SPLIT  = 4;
constexpr int QPB    = 128;
constexpr int THREADS = QPB * SPLIT;          // 512
constexpr int SUBLEN  = N_ / SPLIT;           // 2048 (1024 pairs/thread)
constexpr int GROUP   = 16;                   // candidates per group (8 pairs)
constexpr int NGROUPS = SUBLEN / GROUP;       // 128
constexpr int WARM    = 6;                    // warm-up groups (96 candidates)
constexpr int BPB     = N_ / QPB;             // 64
constexpr int NBLOCKS = B_ * BPB;             // 128 -> 1 block/SM
constexpr int GTOT    = NBLOCKS * THREADS;    // 65536
constexpr int LOGCAP  = 160;
constexpr u64 STRIDEB = (u64)GTOT * 16ull;    // 1MB = 2^20 (16B pair entries)
constexpr int SMEM_BYTES = N_ * 16;           // 128KB point staging
}

__device__ float g_partials[NBLOCKS];
__device__ uint4 g_log[(size_t)LOGCAP * GTOT];   // 160MB static scratch (legal)

__device__ __forceinline__ u64 pk2(float a, float b) {
    u64 r; asm("mov.b64 %0, {%1, %2};" : "=l"(r) : "f"(a), "f"(b)); return r;
}
__device__ __forceinline__ u64 fma2(u64 a, u64 b, u64 c) {
    u64 d; asm("fma.rn.f32x2 %0, %1, %2, %3;" : "=l"(d) : "l"(a), "l"(b), "l"(c)); return d;
}
__device__ __forceinline__ u64 add2(u64 a, u64 b) {
    u64 d; asm("add.rn.f32x2 %0, %1, %2;" : "=l"(d) : "l"(a), "l"(b)); return d;
}
__device__ __forceinline__ void unpk(u64 v, u32& lo, u32& hi) {
    asm("mov.b64 {%0, %1}, %2;" : "=r"(lo), "=r"(hi) : "l"(v));
}
__device__ __forceinline__ u32 umn(u32 a, u32 b) { return a < b ? a : b; }
__device__ __forceinline__ float uasf(u32 x) { return __uint_as_float(x); }

// Branchless float sorted-insert (keys strictly positive -> total order fine).
__device__ __forceinline__ void ins11f(float c, float (&kd)[KP1]) {
#pragma unroll
    for (int t = 0; t < KP1; ++t) {
        const float lo = fminf(c, kd[t]);
        const float hi = fmaxf(c, kd[t]);
        kd[t] = lo; c = hi;
    }
}
// u32 variant for recovery/merge (positive-float bit patterns + tags).
__device__ __forceinline__ void ins11u(u32 c, u32 (&kd)[KP1]) {
#pragma unroll
    for (int t = 0; t < KP1; ++t) {
        const u32 lo = umn(c, kd[t]);
        const u32 hi = (c > kd[t]) ? c : kd[t];
        kd[t] = lo; c = hi;
    }
}

// Predicated PAIR log: if pm < thr, store {klo, khi, jabs, jabs}, bump addr.
__device__ __forceinline__ void logpair(u64& addr, float pm, float thr,
                                        u32 klo, u32 khi, u32 jabs) {
    asm volatile(
        "{\n\t.reg .pred p;\n\t"
        "setp.lt.f32 p, %1, %2;\n\t"
        "@p st.global.v4.b32 [%0], {%3, %4, %5, %5};\n\t"
        "@p add.u64 %0, %0, %6;\n\t}"
        : "+l"(addr)
        : "f"(pm), "f"(thr), "r"(klo), "r"(khi), "r"(jabs), "l"(STRIDEB)
        : "memory");
}

__global__ __launch_bounds__(THREADS, 1)
void knn_lap_loss_kernel(const float* __restrict__ p1, const float* __restrict__ p2) {
    extern __shared__ unsigned char smem_raw[];
    float4* buf = reinterpret_cast<float4*>(smem_raw);

    const int tid   = threadIdx.x;
    const int gtid  = blockIdx.x * THREADS + tid;
    const int b     = blockIdx.x / BPB;
    const int qbase = (blockIdx.x % BPB) * QPB;
    const float* __restrict__ p1b = p1 + (size_t)b * N_ * 3;
    const float* __restrict__ p2b = p2 + (size_t)b * N_ * 3;

    // ---- Phase 1: stage pairs: buf[2p]={x0,x1,y0,y1}, buf[2p+1]={z0,z1,w0,w1} ----
    for (int p = tid; p < N_ / 2; p += THREADS) {
        const int a = 2 * p, c = 2 * p + 1;
        float xa = p1b[a*3+0], ya = p1b[a*3+1], za = p1b[a*3+2];
        float xb = p1b[c*3+0], yb = p1b[c*3+1], zb = p1b[c*3+2];
        float wa = fmaf(xa, xa, fmaf(ya, ya, za * za));
        float wb = fmaf(xb, xb, fmaf(yb, yb, zb * zb));
        buf[2*p]   = make_float4(xa, xb, ya, yb);
        buf[2*p+1] = make_float4(za, zb, wa, wb);
    }
    __syncthreads();

    // ---- Query constants. key = dist^2 + 1 > 0 strictly. ----
    const int q   = tid & (QPB - 1);    // consecutive within warp -> LDS broadcast
    const int sub = tid >> 7;           // 0..3 (constant within warp)
    const int qi  = qbase + q;
    float qx, qy, qz, qw;
    {
        const int p = qi >> 1, h = qi & 1;
        const float4 A = buf[2*p], C = buf[2*p+1];
        qx = h ? A.y : A.x;  qy = h ? A.w : A.z;
        qz = h ? C.y : C.x;  qw = h ? C.w : C.z;
    }
    const u64 m2x2 = pk2(-2.0f*qx, -2.0f*qx);
    const u64 m2y2 = pk2(-2.0f*qy, -2.0f*qy);
    const u64 m2z2 = pk2(-2.0f*qz, -2.0f*qz);
    const float qb = qw + 1.0f;
    const u64 qb2  = pk2(qb, qb);

    float kd[KP1];
#pragma unroll
    for (int t = 0; t < KP1; ++t) kd[t] = 3.0e38f;

    u64 addr        = (u64)(g_log + gtid);
    const u64 base  = addr;
    const u64 limit = base + (u64)(LOGCAP - 8) * STRIDEB;

    const int jbeg = sub * SUBLEN;

    // ---- Phase 2a: warm-up. Pair-min chain insert (22 FMNMX/pair, not 44).
    // Recall: kd[10] = 11th smallest pair-min; >=11 distinct pairs have
    // pm <= kd[10], each contributes >=1 key <= kd[10] => kd[10] >= true 11th
    // key. Any top-11 key k < thr => pm <= k < thr => its pair (BOTH keys)
    // logged. First 11 pairs always log (thr=INF) => recovery >= 22 keys. ----
    for (int g = 0; g < WARM; ++g) {
        const int jg = jbeg + g * GROUP;
        const int pb = jg >> 1;
#pragma unroll
        for (int pp = 0; pp < GROUP / 2; ++pp) {
            const float4 A = buf[2*(pb+pp)], C = buf[2*(pb+pp)+1];
            u64 acc = add2(pk2(C.z, C.w), qb2);
            acc = fma2(pk2(A.x, A.y), m2x2, acc);
            acc = fma2(pk2(A.z, A.w), m2y2, acc);
            acc = fma2(pk2(C.x, C.y), m2z2, acc);
            u32 klo, khi; unpk(acc, klo, khi);
            const float pm = fminf(uasf(klo), uasf(khi));
            const float thr = (addr <= limit) ? kd[KP1-1] : 0.0f;
            logpair(addr, pm, thr, klo, khi, (u32)(jg + 2*pp));
            ins11f(pm, kd);
        }
    }

    // ---- Phase 2b: main scan (R11 structure verbatim). Per pair: 4 wide-FMA
    // + FMNMX + predicated STG. Per group of 8 pairs: fresh thr, 7-op
    // min-tree, one chain insert. ----
    for (int g = WARM; g < NGROUPS; ++g) {
        const int jg = jbeg + g * GROUP;
        const int pb = jg >> 1;
        const float thr = (addr <= limit) ? kd[KP1-1] : 0.0f;
        float pm[GROUP / 2];
#pragma unroll
        for (int pp = 0; pp < GROUP / 2; ++pp) {
            const float4 A = buf[2*(pb+pp)], C = buf[2*(pb+pp)+1];
            u64 acc = add2(pk2(C.z, C.w), qb2);
            acc = fma2(pk2(A.x, A.y), m2x2, acc);
            acc = fma2(pk2(A.z, A.w), m2y2, acc);
            acc = fma2(pk2(C.x, C.y), m2z2, acc);
            u32 klo, khi; unpk(acc, klo, khi);
            pm[pp] = fminf(uasf(klo), uasf(khi));
            logpair(addr, pm[pp], thr, klo, khi, (u32)(jg + 2*pp));
        }
        const float m0 = fminf(fminf(pm[0], pm[1]), fminf(pm[2], pm[3]));
        const float m1 = fminf(fminf(pm[4], pm[5]), fminf(pm[6], pm[7]));
        ins11f(fminf(m0, m1), kd);
    }

    // ---- Phase 3: exact recovery. Tag = (slot<<1)|half in 9 masked key bits. ----
    const u32 cnt = (u32)((addr - base) >> 20);   // STRIDEB = 2^20
    u32 rc[KP1];
#pragma unroll
    for (int t = 0; t < KP1; ++t) rc[t] = 0xFFFFFFFFu;
    for (u32 i = 0; i < cnt; ++i) {
        const uint4 e = *reinterpret_cast<const uint4*>(base + (u64)i * STRIDEB);
        ins11u((e.x & 0xFFFFFE00u) | (i << 1) | 0u, rc);
        ins11u((e.y & 0xFFFFFE00u) | (i << 1) | 1u, rc);
    }

    __syncthreads();   // done reading staged points; smem reused below

    // ---- Phase 4: decode indices, dump sorted lists to smem ----
    u32* sval = reinterpret_cast<u32*>(smem_raw);
    u32* sidx = sval + THREADS * KP1;
    {
        const int dbase = (q * SPLIT + sub) * KP1;
#pragma unroll
        for (int r = 0; r < KP1; ++r) {
            const u32 slot = (rc[r] >> 1) & 0xFFu;
            const u32 h    = rc[r] & 1u;
            const uint4 e  = *reinterpret_cast<const uint4*>(base + (u64)slot * STRIDEB);
            sval[dbase + r] = rc[r];
            sidx[dbase + r] = e.z + h;
        }
    }
    __syncthreads();

    // ---- Phase 5: sub==0 threads 4-way merge + gather + per-query L1 ----
    float acc = 0.0f;
    if (sub == 0) {
        const u32* v0 = sval + (q * SPLIT + 0) * KP1;
        const u32* v1 = sval + (q * SPLIT + 1) * KP1;
        const u32* v2 = sval + (q * SPLIT + 2) * KP1;
        const u32* v3 = sval + (q * SPLIT + 3) * KP1;
        const u32* i0 = sidx + (q * SPLIT + 0) * KP1;
        const u32* i1 = sidx + (q * SPLIT + 1) * KP1;
        const u32* i2 = sidx + (q * SPLIT + 2) * KP1;
        const u32* i3 = sidx + (q * SPLIT + 3) * KP1;

        int c0 = 0, c1 = 0, c2 = 0, c3 = 0;
        u32 nidx[KP1];
#pragma unroll
        for (int r = 0; r < KP1; ++r) {
            const u32 h0 = v0[c0], h1 = v1[c1], h2 = v2[c2], h3 = v3[c3];
            const u32 m = umn(umn(h0, h1), umn(h2, h3));
            u32 bi;
            if (m == h0)      { bi = i0[c0]; ++c0; }
            else if (m == h1) { bi = i1[c1]; ++c1; }
            else if (m == h2) { bi = i2[c2]; ++c2; }
            else              { bi = i3[c3]; ++c3; }
            nidx[r] = bi;
        }

        // nidx[0] is self (key = 1.0, global min) -> neighbors are nidx[1..10]
        float sx = 0.0f, sy = 0.0f, sz = 0.0f;
#pragma unroll
        for (int r = 1; r < KP1; ++r) {
            const int bi = (int)nidx[r];
            sx += p1b[bi*3+0] - p2b[bi*3+0];
            sy += p1b[bi*3+1] - p2b[bi*3+1];
            sz += p1b[bi*3+2] - p2b[bi*3+2];
        }
        const float dqx = p1b[qi*3+0] - p2b[qi*3+0];
        const float dqy = p1b[qi*3+1] - p2b[qi*3+1];
        const float dqz = p1b[qi*3+2] - p2b[qi*3+2];
        const float inv_k = 1.0f / (float)KNN;
        acc = fabsf(fmaf(sx, inv_k, -dqx))
            + fabsf(fmaf(sy, inv_k, -dqy))
            + fabsf(fmaf(sz, inv_k, -dqz));
    }

    // ---- Phase 6: deterministic block reduction ----
    float* red = reinterpret_cast<float*>(sval + 2 * THREADS * KP1);
    red[tid] = acc;
    __syncthreads();
#pragma unroll
    for (int s = THREADS / 2; s > 0; s >>= 1) {
        if (tid < s) red[tid] += red[tid + s];
        __syncthreads();
    }
    if (tid == 0) g_partials[blockIdx.x] = red[0];
}

__global__ void final_reduce_kernel(float* __restrict__ out) {
    __shared__ float s[NBLOCKS];
    const int t = threadIdx.x;
    s[t] = g_partials[t];
    __syncthreads();
#pragma unroll
    for (int st = NBLOCKS / 2; st > 0; st >>= 1) {
        if (t < st) s[t] += s[t + st];
        __syncthreads();
    }
    if (t == 0) out[0] = s[0] * (1.0f / (float)(B_ * N_ * 3));
}

extern "C" void kernel_launch(void* const* d_in, const int* in_sizes, int n_in,
                              void* d_out, int out_size) {
    const float* p1 = (const float*)d_in[0];
    const float* p2 = (const float*)d_in[1];
    (void)in_sizes; (void)n_in; (void)out_size;

    cudaFuncSetAttribute(knn_lap_loss_kernel,
                         cudaFuncAttributeMaxDynamicSharedMemorySize, SMEM_BYTES);
    knn_lap_loss_kernel<<<NBLOCKS, THREADS, SMEM_BYTES>>>(p1, p2);
    final_reduce_kernel<<<1, NBLOCKS>>>((float*)d_out);
}